// round 1
// baseline (speedup 1.0000x reference)
#include <cuda_runtime.h>
#include <cuda_fp16.h>

// Problem constants (fixed shapes)
#define BB_  2
#define SS_  2048
#define DD_  1024
#define HH_  16
#define HDIM 64

// Scratch: fp16 Q/K/V in [B, H, S, hd] layout (8 MB each), packed mask bits (1 MB)
__device__ __half g_Q[(size_t)BB_ * HH_ * SS_ * HDIM];
__device__ __half g_K[(size_t)BB_ * HH_ * SS_ * HDIM];
__device__ __half g_V[(size_t)BB_ * HH_ * SS_ * HDIM];
__device__ unsigned int g_mb[(size_t)BB_ * SS_ * SS_ / 32];

// ---------------------------------------------------------------------------
// mma.sync m16n8k16 fp16 -> fp32
// ---------------------------------------------------------------------------
__device__ __forceinline__ void mma16816(float (&c)[4], const unsigned (&a)[4],
                                         const unsigned (&b)[2]) {
    asm volatile(
        "mma.sync.aligned.m16n8k16.row.col.f32.f16.f16.f32 "
        "{%0,%1,%2,%3}, {%4,%5,%6,%7}, {%8,%9}, {%0,%1,%2,%3};\n"
        : "+f"(c[0]), "+f"(c[1]), "+f"(c[2]), "+f"(c[3])
        : "r"(a[0]), "r"(a[1]), "r"(a[2]), "r"(a[3]), "r"(b[0]), "r"(b[1]));
}

__device__ __forceinline__ unsigned pack_h2(float lo, float hi) {
    __half2 h = __floats2half2_rn(lo, hi);
    return *reinterpret_cast<unsigned*>(&h);
}

// ---------------------------------------------------------------------------
// Kernel 0: pack mask (int32, nonzero==keep) into bitmask
// ---------------------------------------------------------------------------
__global__ void pack_mask_kernel(const int* __restrict__ mask) {
    int idx = blockIdx.x * 256 + threadIdx.x;
    int m = mask[idx];
    unsigned bal = __ballot_sync(0xffffffffu, m != 0);
    if ((threadIdx.x & 31) == 0) g_mb[idx >> 5] = bal;
}

// ---------------------------------------------------------------------------
// Kernel 1: projection GEMM  C[m,n] = sum_k X[m,k] * W[n,k] + bias[n]
// X: [4096, 1024] fp32, W: [1024, 1024] fp32 (row-major [out,in]),
// output fp16 into g_{Q,K,V} with [B,H,S,hd] layout.
// Block tile 128x128x32, 8 warps (2 M x 4 N), warp tile 64x32.
// ---------------------------------------------------------------------------
__global__ __launch_bounds__(256) void proj_kernel(const float* __restrict__ X,
                                                   const float* __restrict__ W,
                                                   const float* __restrict__ bias,
                                                   int which) {
    __shared__ __align__(16) __half sA[128 * 40];
    __shared__ __align__(16) __half sB[128 * 40];

    __half* out = (which == 0) ? g_Q : (which == 1) ? g_K : g_V;

    const int tid = threadIdx.x;
    const int warp = tid >> 5, lane = tid & 31;
    const int g = lane >> 2, t = lane & 3;
    const int wm = warp & 1, wn = warp >> 1;
    const int m0 = blockIdx.y * 128, n0 = blockIdx.x * 128;

    float acc[4][4][4];
#pragma unroll
    for (int mi = 0; mi < 4; mi++)
#pragma unroll
        for (int ni = 0; ni < 4; ni++)
#pragma unroll
            for (int j = 0; j < 4; j++) acc[mi][ni][j] = 0.f;

    for (int kk = 0; kk < DD_; kk += 32) {
#pragma unroll
        for (int i = 0; i < 4; i++) {
            int idx = tid + i * 256;        // 0..1023
            int row = idx >> 3, c4 = idx & 7;
            float4 va = *(const float4*)(X + (size_t)(m0 + row) * DD_ + kk + c4 * 4);
            __half2* pa = (__half2*)(sA + row * 40 + c4 * 4);
            pa[0] = __floats2half2_rn(va.x, va.y);
            pa[1] = __floats2half2_rn(va.z, va.w);
            float4 vb = *(const float4*)(W + (size_t)(n0 + row) * DD_ + kk + c4 * 4);
            __half2* pb = (__half2*)(sB + row * 40 + c4 * 4);
            pb[0] = __floats2half2_rn(vb.x, vb.y);
            pb[1] = __floats2half2_rn(vb.z, vb.w);
        }
        __syncthreads();

#pragma unroll
        for (int k16 = 0; k16 < 32; k16 += 16) {
            unsigned a[4][4], b[4][2];
#pragma unroll
            for (int mi = 0; mi < 4; mi++) {
                const __half* base = sA + (wm * 64 + mi * 16 + g) * 40 + k16 + 2 * t;
                a[mi][0] = *(const unsigned*)(base);
                a[mi][1] = *(const unsigned*)(base + 8 * 40);
                a[mi][2] = *(const unsigned*)(base + 8);
                a[mi][3] = *(const unsigned*)(base + 8 * 40 + 8);
            }
#pragma unroll
            for (int ni = 0; ni < 4; ni++) {
                const __half* base = sB + (wn * 32 + ni * 8 + g) * 40 + k16 + 2 * t;
                b[ni][0] = *(const unsigned*)(base);
                b[ni][1] = *(const unsigned*)(base + 8);
            }
#pragma unroll
            for (int mi = 0; mi < 4; mi++)
#pragma unroll
                for (int ni = 0; ni < 4; ni++) mma16816(acc[mi][ni], a[mi], b[ni]);
        }
        __syncthreads();
    }

    // Epilogue: add bias, convert to fp16, scatter into [B,H,S,hd]
#pragma unroll
    for (int mi = 0; mi < 4; mi++) {
        int mrow = m0 + wm * 64 + mi * 16 + g;
        int bidx = mrow >> 11;          // batch
        int s = mrow & (SS_ - 1);
#pragma unroll
        for (int ni = 0; ni < 4; ni++) {
            int ncol = n0 + wn * 32 + ni * 8 + 2 * t;
            float b0 = bias[ncol], b1 = bias[ncol + 1];
            int h = ncol >> 6, d = ncol & 63;
            size_t base = (((size_t)(bidx * HH_ + h) * SS_ + s) * HDIM + d);
            *(__half2*)(out + base) =
                __floats2half2_rn(acc[mi][ni][0] + b0, acc[mi][ni][1] + b1);
            *(__half2*)(out + base + 8 * HDIM) =
                __floats2half2_rn(acc[mi][ni][2] + b0, acc[mi][ni][3] + b1);
        }
    }
}

// ---------------------------------------------------------------------------
// Kernel 2: flash attention. Grid (S/128, B*H). 8 warps, each owns 16 Q rows.
// KV tiles of 64. fp16 mma, fp32 online softmax, output fp32 [B,S,D].
// ---------------------------------------------------------------------------
__global__ __launch_bounds__(256) void attn_kernel(float* __restrict__ out) {
    __shared__ __align__(16) __half sK[64 * 72];
    __shared__ __align__(16) __half sVt[64 * 72];

    const int tid = threadIdx.x;
    const int warp = tid >> 5, lane = tid & 31;
    const int g = lane >> 2, t = lane & 3;

    const int bh = blockIdx.y;           // b*16 + h
    const int bidx = bh >> 4, h = bh & 15;
    const int q0 = blockIdx.x * 128;
    const int qr = q0 + warp * 16 + g;   // thread's row0 (row1 = qr + 8)

    // Q fragments held in registers for the whole KV loop
    const __half* Qp = g_Q + ((size_t)bh * SS_ + q0 + warp * 16) * HDIM;
    unsigned qa[4][4];
#pragma unroll
    for (int kt = 0; kt < 4; kt++) {
        const __half* base = Qp + g * HDIM + kt * 16 + 2 * t;
        qa[kt][0] = *(const unsigned*)(base);
        qa[kt][1] = *(const unsigned*)(base + 8 * HDIM);
        qa[kt][2] = *(const unsigned*)(base + 8);
        qa[kt][3] = *(const unsigned*)(base + 8 * HDIM + 8);
    }

    const __half* Kp = g_K + (size_t)bh * SS_ * HDIM;
    const __half* Vp = g_V + (size_t)bh * SS_ * HDIM;

    float o[8][4];
#pragma unroll
    for (int i = 0; i < 8; i++)
#pragma unroll
        for (int j = 0; j < 4; j++) o[i][j] = 0.f;
    float mrun0 = -INFINITY, mrun1 = -INFINITY, l0 = 0.f, l1 = 0.f;

    const unsigned long long* mb64 = (const unsigned long long*)g_mb;
    const size_t mbase = ((size_t)bidx * SS_ + qr) * (SS_ / 64);

    for (int tile = 0; tile < SS_ / 64; tile++) {
        const int kv0 = tile * 64;
        // cooperative load: K as-is, V transposed
#pragma unroll
        for (int i = 0; i < 2; i++) {
            int idx = tid + i * 256;     // 0..511
            int row = idx >> 3, c = idx & 7;
            uint4 kvv = *(const uint4*)(Kp + (size_t)(kv0 + row) * HDIM + c * 8);
            *(uint4*)(sK + row * 72 + c * 8) = kvv;
            uint4 vvv = *(const uint4*)(Vp + (size_t)(kv0 + row) * HDIM + c * 8);
            const __half* hv = (const __half*)&vvv;
#pragma unroll
            for (int j = 0; j < 8; j++) sVt[(c * 8 + j) * 72 + row] = hv[j];
        }
        __syncthreads();

        // S = Q K^T
        float sc[8][4];
#pragma unroll
        for (int i = 0; i < 8; i++)
#pragma unroll
            for (int j = 0; j < 4; j++) sc[i][j] = 0.f;
#pragma unroll
        for (int kt = 0; kt < 4; kt++)
#pragma unroll
            for (int ni = 0; ni < 8; ni++) {
                unsigned bk[2];
                const __half* base = sK + (ni * 8 + g) * 72 + kt * 16 + 2 * t;
                bk[0] = *(const unsigned*)(base);
                bk[1] = *(const unsigned*)(base + 8);
                mma16816(sc[ni], qa[kt], bk);
            }

        // scale + mask (matches reference: scale first, masked -> exactly -1e9)
        unsigned long long mr0 = mb64[mbase + tile];
        unsigned long long mr1 = mb64[mbase + 8 * (SS_ / 64) + tile];
        float mx0 = -INFINITY, mx1 = -INFINITY;
#pragma unroll
        for (int ni = 0; ni < 8; ni++) {
            int c0 = ni * 8 + 2 * t, c1 = c0 + 1;
            float v0 = sc[ni][0] * 0.125f; if (!((mr0 >> c0) & 1ull)) v0 = -1e9f;
            float v1 = sc[ni][1] * 0.125f; if (!((mr0 >> c1) & 1ull)) v1 = -1e9f;
            float v2 = sc[ni][2] * 0.125f; if (!((mr1 >> c0) & 1ull)) v2 = -1e9f;
            float v3 = sc[ni][3] * 0.125f; if (!((mr1 >> c1) & 1ull)) v3 = -1e9f;
            sc[ni][0] = v0; sc[ni][1] = v1; sc[ni][2] = v2; sc[ni][3] = v3;
            mx0 = fmaxf(mx0, fmaxf(v0, v1));
            mx1 = fmaxf(mx1, fmaxf(v2, v3));
        }
        mx0 = fmaxf(mx0, __shfl_xor_sync(0xffffffffu, mx0, 1));
        mx0 = fmaxf(mx0, __shfl_xor_sync(0xffffffffu, mx0, 2));
        mx1 = fmaxf(mx1, __shfl_xor_sync(0xffffffffu, mx1, 1));
        mx1 = fmaxf(mx1, __shfl_xor_sync(0xffffffffu, mx1, 2));

        float nm0 = fmaxf(mrun0, mx0), nm1 = fmaxf(mrun1, mx1);
        float f0 = __expf(mrun0 - nm0), f1 = __expf(mrun1 - nm1);
        mrun0 = nm0; mrun1 = nm1;

        float sum0 = 0.f, sum1 = 0.f;
        unsigned pa[4][4];
#pragma unroll
        for (int kt = 0; kt < 4; kt++) {
            int jl = 2 * kt, jh = 2 * kt + 1;
            float p00 = __expf(sc[jl][0] - nm0), p01 = __expf(sc[jl][1] - nm0);
            float p02 = __expf(sc[jl][2] - nm1), p03 = __expf(sc[jl][3] - nm1);
            float p10 = __expf(sc[jh][0] - nm0), p11 = __expf(sc[jh][1] - nm0);
            float p12 = __expf(sc[jh][2] - nm1), p13 = __expf(sc[jh][3] - nm1);
            sum0 += p00 + p01 + p10 + p11;
            sum1 += p02 + p03 + p12 + p13;
            pa[kt][0] = pack_h2(p00, p01);
            pa[kt][1] = pack_h2(p02, p03);
            pa[kt][2] = pack_h2(p10, p11);
            pa[kt][3] = pack_h2(p12, p13);
        }
        sum0 += __shfl_xor_sync(0xffffffffu, sum0, 1);
        sum0 += __shfl_xor_sync(0xffffffffu, sum0, 2);
        sum1 += __shfl_xor_sync(0xffffffffu, sum1, 1);
        sum1 += __shfl_xor_sync(0xffffffffu, sum1, 2);
        l0 = l0 * f0 + sum0;
        l1 = l1 * f1 + sum1;

#pragma unroll
        for (int nd = 0; nd < 8; nd++) {
            o[nd][0] *= f0; o[nd][1] *= f0; o[nd][2] *= f1; o[nd][3] *= f1;
        }
        // O += P V
#pragma unroll
        for (int kt = 0; kt < 4; kt++)
#pragma unroll
            for (int nd = 0; nd < 8; nd++) {
                unsigned bv[2];
                const __half* base = sVt + (nd * 8 + g) * 72 + kt * 16 + 2 * t;
                bv[0] = *(const unsigned*)(base);
                bv[1] = *(const unsigned*)(base + 8);
                mma16816(o[nd], pa[kt], bv);
            }
        __syncthreads();
    }

    float inv0 = 1.f / l0, inv1 = 1.f / l1;
    float* Op0 = out + ((size_t)bidx * SS_ + qr) * DD_ + h * HDIM;
    float* Op1 = Op0 + 8 * DD_;
#pragma unroll
    for (int nd = 0; nd < 8; nd++) {
        int d = nd * 8 + 2 * t;
        *(float2*)(Op0 + d) = make_float2(o[nd][0] * inv0, o[nd][1] * inv0);
        *(float2*)(Op1 + d) = make_float2(o[nd][2] * inv1, o[nd][3] * inv1);
    }
}

// ---------------------------------------------------------------------------
extern "C" void kernel_launch(void* const* d_in, const int* in_sizes, int n_in,
                              void* d_out, int out_size) {
    (void)in_sizes; (void)n_in; (void)out_size;
    const float* query = (const float*)d_in[0];
    const float* key   = (const float*)d_in[1];
    const float* value = (const float*)d_in[2];
    const int*   mask  = (const int*)d_in[3];
    const float* Wq = (const float*)d_in[4];
    const float* bq = (const float*)d_in[5];
    const float* Wk = (const float*)d_in[6];
    const float* bk = (const float*)d_in[7];
    const float* Wv = (const float*)d_in[8];
    const float* bv = (const float*)d_in[9];

    pack_mask_kernel<<<(BB_ * SS_ * SS_) / 256, 256>>>(mask);

    dim3 gp(DD_ / 128, (BB_ * SS_) / 128);   // (8, 32)
    proj_kernel<<<gp, 256>>>(query, Wq, bq, 0);
    proj_kernel<<<gp, 256>>>(key,   Wk, bk, 1);
    proj_kernel<<<gp, 256>>>(value, Wv, bv, 2);

    dim3 ga(SS_ / 128, BB_ * HH_);           // (16, 32)
    attn_kernel<<<ga, 256>>>((float*)d_out);
}